// round 2
// baseline (speedup 1.0000x reference)
#include <cuda_runtime.h>
#include <math.h>

// Problem constants
#define B_ 32
#define C_ 512
#define S_ 1024   // H*W
#define K_ 256    // HID
#define M_ 256    // MEM

// Scratch (no allocations allowed)
__device__ float g_hproj[B_ * K_];   // h @ W_lin^T + b_lin
__device__ float g_a2[B_ * S_];      // pre-softmax logits

// ---------------------------------------------------------------------------
// Kernel 1: hproj[b][k] = sum_m h[b][m] * W_lin[k][m] + b_lin[k]
// ---------------------------------------------------------------------------
__global__ void hproj_kernel(const float* __restrict__ h,
                             const float* __restrict__ Wl,
                             const float* __restrict__ bl) {
    int b = blockIdx.x;
    int k = threadIdx.x;           // 256 threads
    __shared__ float hs[M_];
    hs[k] = h[b * M_ + k];
    __syncthreads();
    float s = bl[k];
    const float* wrow = Wl + (size_t)k * M_;
#pragma unroll 8
    for (int m = 0; m < M_; m++) s += hs[m] * wrow[m];
    g_hproj[b * K_ + k] = s;
}

// ---------------------------------------------------------------------------
// Kernel 2: fused GEMM + tanh + attention reduction.
//   For each batch b and 128-wide tile of spatial positions s:
//     Y[k][s] = sum_c W_conv1[k][c] * x[b][c][s]      (k=0..255, done in 2 chunks of 128)
//     a2[s]  += sum_k tanh(Y[k][s] + hproj[b][k]) * W_attn[k]
// Block tile: 128(k) x 128(s), BK=16, thread tile 8x8, 256 threads.
// ---------------------------------------------------------------------------
#define BM 128
#define BN 128
#define BK 16
#define WPAD 4   // padding to break bank conflicts on Ws stores

__global__ __launch_bounds__(256, 2)
void attn_logits_kernel(const float* __restrict__ x,
                        const float* __restrict__ Wc,
                        const float* __restrict__ Wattn) {
    const int stile = blockIdx.x;   // 0..7
    const int b     = blockIdx.y;   // 0..31
    const int tid   = threadIdx.x;
    const int tx    = tid & 15;     // s-dim thread coord (0..15)
    const int ty    = tid >> 4;     // k-dim thread coord (0..15)

    __shared__ float Ws[BK][BM + WPAD];  // [c][k]
    __shared__ float Xs[BK][BN];         // [c][s]
    __shared__ float a2s[BN];

    if (tid < BN) a2s[tid] = 0.0f;

    const float* xb = x + (size_t)b * C_ * S_ + (size_t)stile * BN;

    for (int kbase = 0; kbase < K_; kbase += BM) {
        float acc[8][8];
#pragma unroll
        for (int i = 0; i < 8; i++)
#pragma unroll
            for (int j = 0; j < 8; j++) acc[i][j] = 0.0f;

        for (int c0 = 0; c0 < C_; c0 += BK) {
            // Load W tile: 128 k-rows x 16 c-cols -> Ws[c][k] (transposed in smem)
            {
                const int cw = tid & 15;   // c within tile
                const int kw = tid >> 4;   // base k, stride 16
#pragma unroll
                for (int r = 0; r < 8; r++) {
                    const int k = kw + r * 16;
                    Ws[cw][k] = Wc[(size_t)(kbase + k) * C_ + (c0 + cw)];
                }
            }
            // Load X tile: 16 c-rows x 128 s-cols, vectorized float4
            {
#pragma unroll
                for (int r = 0; r < 2; r++) {
                    const int idx = tid + r * 256;       // 0..511 float4 slots
                    const int cr  = idx >> 5;            // c row 0..15
                    const int sc  = (idx & 31) << 2;     // s col (x4)
                    float4 v = *(const float4*)&xb[(size_t)(c0 + cr) * S_ + sc];
                    *(float4*)&Xs[cr][sc] = v;
                }
            }
            __syncthreads();

#pragma unroll
            for (int cc = 0; cc < BK; cc++) {
                float4 w0 = *(const float4*)&Ws[cc][ty * 8];
                float4 w1 = *(const float4*)&Ws[cc][ty * 8 + 4];
                float4 x0 = *(const float4*)&Xs[cc][tx * 8];
                float4 x1 = *(const float4*)&Xs[cc][tx * 8 + 4];
                float wv[8] = {w0.x, w0.y, w0.z, w0.w, w1.x, w1.y, w1.z, w1.w};
                float xv[8] = {x0.x, x0.y, x0.z, x0.w, x1.x, x1.y, x1.z, x1.w};
#pragma unroll
                for (int i = 0; i < 8; i++)
#pragma unroll
                    for (int j = 0; j < 8; j++)
                        acc[i][j] += wv[i] * xv[j];
            }
            __syncthreads();
        }

        // Epilogue for this k-chunk: tanh + attention-weight reduction over k
        float part[8];
#pragma unroll
        for (int j = 0; j < 8; j++) part[j] = 0.0f;
#pragma unroll
        for (int i = 0; i < 8; i++) {
            const int k   = kbase + ty * 8 + i;
            const float hv = g_hproj[b * K_ + k];
            const float wa = Wattn[k];
#pragma unroll
            for (int j = 0; j < 8; j++)
                part[j] += tanhf(acc[i][j] + hv) * wa;
        }
#pragma unroll
        for (int j = 0; j < 8; j++)
            atomicAdd(&a2s[tx * 8 + j], part[j]);
    }

    __syncthreads();
    if (tid < BN)
        g_a2[b * S_ + stile * BN + tid] = a2s[tid];
}

// ---------------------------------------------------------------------------
// Kernel 3: softmax over S=1024 per batch. 256 threads, 4 values each.
// ---------------------------------------------------------------------------
__global__ void softmax_kernel(float* __restrict__ a3_out) {
    const int b = blockIdx.x;
    const int tid = threadIdx.x;
    __shared__ float red[256];

    float v[4];
#pragma unroll
    for (int i = 0; i < 4; i++) v[i] = g_a2[b * S_ + tid + i * 256];

    float mx = fmaxf(fmaxf(v[0], v[1]), fmaxf(v[2], v[3]));
    red[tid] = mx;
    __syncthreads();
    for (int off = 128; off > 0; off >>= 1) {
        if (tid < off) red[tid] = fmaxf(red[tid], red[tid + off]);
        __syncthreads();
    }
    mx = red[0];
    __syncthreads();

    float s = 0.0f;
#pragma unroll
    for (int i = 0; i < 4; i++) { v[i] = expf(v[i] - mx); s += v[i]; }
    red[tid] = s;
    __syncthreads();
    for (int off = 128; off > 0; off >>= 1) {
        if (tid < off) red[tid] += red[tid + off];
        __syncthreads();
    }
    const float inv = 1.0f / red[0];
#pragma unroll
    for (int i = 0; i < 4; i++)
        a3_out[b * S_ + tid + i * 256] = v[i] * inv;
}

// ---------------------------------------------------------------------------
// Kernel 4: context[b][c] = sum_s x[b][c][s] * a3[b][s]
// grid (32 b, 8 c-tiles of 64), block 256 = 8 warps, 8 c's per warp.
// ---------------------------------------------------------------------------
__global__ __launch_bounds__(256)
void context_kernel(const float* __restrict__ x,
                    const float* __restrict__ a3,
                    float* __restrict__ ctx) {
    const int b    = blockIdx.x;
    const int ct   = blockIdx.y;
    const int tid  = threadIdx.x;
    const int w    = tid >> 5;
    const int lane = tid & 31;

    __shared__ float a3s[S_];
    for (int i = tid; i < S_; i += 256) a3s[i] = a3[b * S_ + i];
    __syncthreads();

    for (int cc = 0; cc < 8; cc++) {
        const int c = ct * 64 + w * 8 + cc;
        const float* xr = x + (size_t)b * C_ * S_ + (size_t)c * S_;
        float s = 0.0f;
#pragma unroll 8
        for (int i = lane; i < S_; i += 32) s += xr[i] * a3s[i];
#pragma unroll
        for (int off = 16; off > 0; off >>= 1)
            s += __shfl_down_sync(0xffffffffu, s, off);
        if (lane == 0) ctx[b * C_ + c] = s;
    }
}

// ---------------------------------------------------------------------------
// Launch
// ---------------------------------------------------------------------------
extern "C" void kernel_launch(void* const* d_in, const int* in_sizes, int n_in,
                              void* d_out, int out_size) {
    const float* x  = (const float*)d_in[0];   // [32,512,32,32]
    const float* h  = (const float*)d_in[1];   // [32,256]
    const float* Wc = (const float*)d_in[2];   // [256,512]
    const float* Wl = (const float*)d_in[3];   // [256,256]
    const float* bl = (const float*)d_in[4];   // [256]
    const float* Wa = (const float*)d_in[5];   // [256]

    float* out = (float*)d_out;
    float* a3  = out;             // [32,1024]
    float* ctx = out + B_ * S_;   // [32,512]

    hproj_kernel<<<B_, 256>>>(h, Wl, bl);
    attn_logits_kernel<<<dim3(S_ / BN, B_), 256>>>(x, Wc, Wa);
    softmax_kernel<<<B_, 256>>>(a3);
    context_kernel<<<dim3(B_, 8), 256>>>(x, a3, ctx);
}

// round 4
// speedup vs baseline: 1.8827x; 1.8827x over previous
#include <cuda_runtime.h>
#include <cuda_bf16.h>
#include <math.h>
#include <stdint.h>

#define B_ 32
#define C_ 512
#define S_ 1024
#define K_ 256
#define M_ 256

// ---------------- scratch (no allocs allowed) ----------------
__device__ float g_hproj[B_ * K_];
__device__ float g_a2[B_ * S_];
__device__ __nv_bfloat16 g_Whi[K_ * C_];
__device__ __nv_bfloat16 g_Wlo[K_ * C_];

// ---------------- kernel 0: split W into bf16 hi/lo ----------------
__global__ void wsplit_kernel(const float* __restrict__ Wc) {
    int i = blockIdx.x * 256 + threadIdx.x;   // 512 * 256 = 131072 = K_*C_
    float v = Wc[i];
    __nv_bfloat16 hv = __float2bfloat16(v);
    g_Whi[i] = hv;
    g_Wlo[i] = __float2bfloat16(v - __bfloat162float(hv));
}

// ---------------- kernel 1: hproj ----------------
__global__ void hproj_kernel(const float* __restrict__ h,
                             const float* __restrict__ Wl,
                             const float* __restrict__ bl) {
    int b = blockIdx.x;
    int k = threadIdx.x;
    __shared__ float hs[M_];
    hs[k] = h[b * M_ + k];
    __syncthreads();
    float s = bl[k];
    const float* wrow = Wl + (size_t)k * M_;
#pragma unroll 8
    for (int m = 0; m < M_; m++) s += hs[m] * wrow[m];
    g_hproj[b * K_ + k] = s;
}

// ---------------- kernel 2: mma.sync fused logits ----------------
// C[256k x 128s] = W[256x512] @ x[512x128] per (b, stile), bf16x3 split,
// fp32 accumulators in registers, fused tanh + W_attn k-reduction.
//
// 256 threads = 8 warps: kq = wid>>2 (2 x 64k), ws = wid&3 (4 x 32s).
// Two kp passes (k += 128) share smem tiles; acc[2][4][4][4] per thread.

#define CHUNK_C 64
#define N_CHUNKS (C_ / CHUNK_C)   // 8

// smem stage layout (bytes)
#define PA_ELEM 72                 // W tile pitch in bf16 elems (144B, 16B-aligned)
#define OFF_AHI 0
#define OFF_ALO 36864              // 256*144
#define PX_WORDS 136               // x-pair tile pitch in u32 words (544B; 136%32==8)
#define OFF_XHI 73728
#define OFF_XLO 91136              // +32*544
#define STAGE_BYTES 108544         // +32*544
#define DYN_BYTES (2 * STAGE_BYTES)

extern __shared__ __align__(16) char dyn_smem[];

__device__ __forceinline__ uint32_t pack_bf16x2(float lo, float hi) {
    __nv_bfloat16 a = __float2bfloat16(lo);
    __nv_bfloat16 b = __float2bfloat16(hi);
    return ((uint32_t)__bfloat16_as_ushort(b) << 16) | (uint32_t)__bfloat16_as_ushort(a);
}

__device__ __forceinline__ void mma16816(float* d, uint32_t a0, uint32_t a1,
                                         uint32_t a2, uint32_t a3,
                                         uint32_t b0, uint32_t b1) {
    asm volatile(
        "mma.sync.aligned.m16n8k16.row.col.f32.bf16.bf16.f32 "
        "{%0,%1,%2,%3}, {%4,%5,%6,%7}, {%8,%9}, {%0,%1,%2,%3};"
        : "+f"(d[0]), "+f"(d[1]), "+f"(d[2]), "+f"(d[3])
        : "r"(a0), "r"(a1), "r"(a2), "r"(a3), "r"(b0), "r"(b1));
}

// fill one stage with chunk starting at channel c0
__device__ __forceinline__ void fill_stage(char* st, const float* __restrict__ xb,
                                           int c0, int tid) {
    const int lane = tid & 31;
    const int w    = tid >> 5;
    // --- W tiles: [k][c] bf16, pitch 144B, rows k=0..255, 64 c ---
#pragma unroll
    for (int it = 0; it < 8; it++) {
        const int idx = tid + it * 256;           // 0..2047
        const int k   = idx >> 3;
        const int seg = idx & 7;                  // 16B segment
        const uint4 vh = *((const uint4*)(g_Whi + (size_t)k * C_ + c0) + seg);
        const uint4 vl = *((const uint4*)(g_Wlo + (size_t)k * C_ + c0) + seg);
        *(uint4*)(st + OFF_AHI + k * 144 + seg * 16) = vh;
        *(uint4*)(st + OFF_ALO + k * 144 + seg * 16) = vl;
    }
    // --- x tiles: packed c-pairs. row c2 holds bf16x2{x[2c2][s], x[2c2+1][s]} ---
#pragma unroll
    for (int cc = 0; cc < 4; cc++) {
        const int c2 = w + cc * 8;                // 0..31
        const float* r0 = xb + (size_t)(c0 + 2 * c2) * S_;
        const float* r1 = r0 + S_;
        float4 v0 = *(const float4*)(r0 + lane * 4);
        float4 v1 = *(const float4*)(r1 + lane * 4);
        float h0x = __bfloat162float(__float2bfloat16(v0.x));
        float h0y = __bfloat162float(__float2bfloat16(v0.y));
        float h0z = __bfloat162float(__float2bfloat16(v0.z));
        float h0w = __bfloat162float(__float2bfloat16(v0.w));
        float h1x = __bfloat162float(__float2bfloat16(v1.x));
        float h1y = __bfloat162float(__float2bfloat16(v1.y));
        float h1z = __bfloat162float(__float2bfloat16(v1.z));
        float h1w = __bfloat162float(__float2bfloat16(v1.w));
        uint4 ph, pl;
        ph.x = pack_bf16x2(v0.x, v1.x);  pl.x = pack_bf16x2(v0.x - h0x, v1.x - h1x);
        ph.y = pack_bf16x2(v0.y, v1.y);  pl.y = pack_bf16x2(v0.y - h0y, v1.y - h1y);
        ph.z = pack_bf16x2(v0.z, v1.z);  pl.z = pack_bf16x2(v0.z - h0z, v1.z - h1z);
        ph.w = pack_bf16x2(v0.w, v1.w);  pl.w = pack_bf16x2(v0.w - h0w, v1.w - h1w);
        *(uint4*)(st + OFF_XHI + c2 * 544 + lane * 16) = ph;
        *(uint4*)(st + OFF_XLO + c2 * 544 + lane * 16) = pl;
    }
}

__global__ __launch_bounds__(256, 1)
void attn_logits_mma(const float* __restrict__ x,
                     const float* __restrict__ Wattn) {
    const int stile = blockIdx.x;     // 0..7
    const int b     = blockIdx.y;     // 0..31
    const int tid   = threadIdx.x;
    const int wid   = tid >> 5;
    const int lane  = tid & 31;
    const int g     = lane >> 2;      // 0..7
    const int t     = lane & 3;       // 0..3
    const int kq    = wid >> 2;       // 0..1 (64-k quadrant)
    const int ws    = wid & 3;        // 0..3 (32-s quadrant)

    __shared__ float a2s[128];
    __shared__ float hp_s[K_];
    __shared__ float wa_s[K_];

    char* tiles = dyn_smem;
    const float* xb = x + (size_t)b * C_ * S_ + (size_t)stile * 128;

    // prologue: fill stage 0 + per-CTA scalars
    fill_stage(tiles, xb, 0, tid);
    hp_s[tid] = g_hproj[b * K_ + tid];
    wa_s[tid] = Wattn[tid];
    if (tid < 128) a2s[tid] = 0.0f;
    __syncthreads();

    float acc[2][4][4][4];
#pragma unroll
    for (int kp = 0; kp < 2; kp++)
#pragma unroll
        for (int i = 0; i < 4; i++)
#pragma unroll
            for (int j = 0; j < 4; j++)
#pragma unroll
                for (int r = 0; r < 4; r++) acc[kp][i][j][r] = 0.0f;

    for (int ch = 0; ch < N_CHUNKS; ch++) {
        const int p = ch & 1;
        if (ch + 1 < N_CHUNKS)
            fill_stage(tiles + (p ^ 1) * STAGE_BYTES, xb, (ch + 1) * CHUNK_C, tid);

        const char* st = tiles + p * STAGE_BYTES;
        const __nv_bfloat16* Ahi = (const __nv_bfloat16*)(st + OFF_AHI);
        const __nv_bfloat16* Alo = (const __nv_bfloat16*)(st + OFF_ALO);
        const uint32_t* Xhi = (const uint32_t*)(st + OFF_XHI);
        const uint32_t* Xlo = (const uint32_t*)(st + OFF_XLO);

#pragma unroll
        for (int kt = 0; kt < 4; kt++) {          // 16-c step within chunk
            // B fragments (k-major pairs): b0 rows {2t,2t+1}, b1 rows {2t+8,2t+9}
            uint32_t bh[4][2], blo[4][2];
#pragma unroll
            for (int j = 0; j < 4; j++) {
                const int s = ws * 32 + j * 8 + g;
                bh[j][0]  = Xhi[(kt * 8 + t)     * PX_WORDS + s];
                bh[j][1]  = Xhi[(kt * 8 + t + 4) * PX_WORDS + s];
                blo[j][0] = Xlo[(kt * 8 + t)     * PX_WORDS + s];
                blo[j][1] = Xlo[(kt * 8 + t + 4) * PX_WORDS + s];
            }
#pragma unroll
            for (int kp = 0; kp < 2; kp++) {
#pragma unroll
                for (int i = 0; i < 4; i++) {
                    const int k0 = kp * 128 + kq * 64 + i * 16;
                    const __nv_bfloat16* arh = Ahi + (size_t)(k0 + g) * PA_ELEM + kt * 16 + 2 * t;
                    const __nv_bfloat16* arl = Alo + (size_t)(k0 + g) * PA_ELEM + kt * 16 + 2 * t;
                    uint32_t ah0 = *(const uint32_t*)(arh);
                    uint32_t ah1 = *(const uint32_t*)(arh + 8 * PA_ELEM);
                    uint32_t ah2 = *(const uint32_t*)(arh + 8);
                    uint32_t ah3 = *(const uint32_t*)(arh + 8 * PA_ELEM + 8);
                    uint32_t al0 = *(const uint32_t*)(arl);
                    uint32_t al1 = *(const uint32_t*)(arl + 8 * PA_ELEM);
                    uint32_t al2 = *(const uint32_t*)(arl + 8);
                    uint32_t al3 = *(const uint32_t*)(arl + 8 * PA_ELEM + 8);
#pragma unroll
                    for (int j = 0; j < 4; j++) {
                        mma16816(acc[kp][i][j], ah0, ah1, ah2, ah3, bh[j][0], bh[j][1]);
                        mma16816(acc[kp][i][j], ah0, ah1, ah2, ah3, blo[j][0], blo[j][1]);
                        mma16816(acc[kp][i][j], al0, al1, al2, al3, bh[j][0], bh[j][1]);
                    }
                }
            }
        }
        __syncthreads();
    }

    // ---- epilogue: tanh + W_attn reduction over k ----
    float part[4][2];
#pragma unroll
    for (int j = 0; j < 4; j++) { part[j][0] = 0.0f; part[j][1] = 0.0f; }

#pragma unroll
    for (int kp = 0; kp < 2; kp++)
#pragma unroll
        for (int i = 0; i < 4; i++)
#pragma unroll
            for (int half = 0; half < 2; half++) {
                const int k = kp * 128 + kq * 64 + i * 16 + half * 8 + g;
                const float hp = hp_s[k];
                const float wa = wa_s[k];
#pragma unroll
                for (int j = 0; j < 4; j++) {
#pragma unroll
                    for (int pc = 0; pc < 2; pc++) {
                        const float y = acc[kp][i][j][half * 2 + pc];
                        part[j][pc] += tanhf(y + hp) * wa;
                    }
                }
            }

    // reduce over the 8 g-lanes (same t) via butterfly
#pragma unroll
    for (int m = 4; m <= 16; m <<= 1)
#pragma unroll
        for (int j = 0; j < 4; j++) {
            part[j][0] += __shfl_xor_sync(0xffffffffu, part[j][0], m);
            part[j][1] += __shfl_xor_sync(0xffffffffu, part[j][1], m);
        }

    if (lane < 4) {   // lane == t
#pragma unroll
        for (int j = 0; j < 4; j++) {
            atomicAdd(&a2s[ws * 32 + j * 8 + 2 * lane + 0], part[j][0]);
            atomicAdd(&a2s[ws * 32 + j * 8 + 2 * lane + 1], part[j][1]);
        }
    }
    __syncthreads();
    if (tid < 128) g_a2[b * S_ + stile * 128 + tid] = a2s[tid];
}

// ---------------- kernel 3: softmax ----------------
__global__ void softmax_kernel(float* __restrict__ a3_out) {
    const int b = blockIdx.x;
    const int tid = threadIdx.x;
    __shared__ float red[256];
    float v[4];
#pragma unroll
    for (int i = 0; i < 4; i++) v[i] = g_a2[b * S_ + tid + i * 256];
    float mx = fmaxf(fmaxf(v[0], v[1]), fmaxf(v[2], v[3]));
    red[tid] = mx;
    __syncthreads();
    for (int off = 128; off > 0; off >>= 1) {
        if (tid < off) red[tid] = fmaxf(red[tid], red[tid + off]);
        __syncthreads();
    }
    mx = red[0];
    __syncthreads();
    float s = 0.0f;
#pragma unroll
    for (int i = 0; i < 4; i++) { v[i] = expf(v[i] - mx); s += v[i]; }
    red[tid] = s;
    __syncthreads();
    for (int off = 128; off > 0; off >>= 1) {
        if (tid < off) red[tid] += red[tid + off];
        __syncthreads();
    }
    const float inv = 1.0f / red[0];
#pragma unroll
    for (int i = 0; i < 4; i++)
        a3_out[b * S_ + tid + i * 256] = v[i] * inv;
}

// ---------------- kernel 4: context ----------------
__global__ __launch_bounds__(256)
void context_kernel(const float* __restrict__ x,
                    const float* __restrict__ a3,
                    float* __restrict__ ctx) {
    const int b  = blockIdx.x;
    const int cg = blockIdx.y;                 // 64 groups of 8 channels
    const int w    = threadIdx.x >> 5;
    const int lane = threadIdx.x & 31;
    const int c = cg * 8 + w;
    const float4* xr = (const float4*)(x + ((size_t)b * C_ + c) * S_);
    const float4* ar = (const float4*)(a3 + (size_t)b * S_);
    float s0 = 0, s1 = 0, s2 = 0, s3 = 0;
#pragma unroll
    for (int it = 0; it < 8; it++) {
        float4 xv = xr[lane + it * 32];
        float4 av = ar[lane + it * 32];
        s0 += xv.x * av.x; s1 += xv.y * av.y;
        s2 += xv.z * av.z; s3 += xv.w * av.w;
    }
    float s = (s0 + s1) + (s2 + s3);
#pragma unroll
    for (int off = 16; off > 0; off >>= 1)
        s += __shfl_down_sync(0xffffffffu, s, off);
    if (lane == 0) ctx[b * C_ + c] = s;
}

// ---------------- launch ----------------
extern "C" void kernel_launch(void* const* d_in, const int* in_sizes, int n_in,
                              void* d_out, int out_size) {
    const float* x  = (const float*)d_in[0];
    const float* h  = (const float*)d_in[1];
    const float* Wc = (const float*)d_in[2];
    const float* Wl = (const float*)d_in[3];
    const float* bl = (const float*)d_in[4];
    const float* Wa = (const float*)d_in[5];

    float* out = (float*)d_out;
    float* a3  = out;
    float* ctx = out + B_ * S_;

    cudaFuncSetAttribute(attn_logits_mma,
                         cudaFuncAttributeMaxDynamicSharedMemorySize, DYN_BYTES);

    wsplit_kernel<<<512, 256>>>(Wc);
    hproj_kernel<<<B_, 256>>>(h, Wl, bl);
    attn_logits_mma<<<dim3(8, B_), 256, DYN_BYTES>>>(x, Wa);
    softmax_kernel<<<B_, 256>>>(a3);
    context_kernel<<<dim3(B_, 64), 256>>>(x, a3, ctx);
}

// round 5
// speedup vs baseline: 2.9366x; 1.5598x over previous
#include <cuda_runtime.h>
#include <cuda_fp16.h>
#include <math.h>
#include <stdint.h>

#define B_ 32
#define C_ 512
#define S_ 1024
#define K_ 256
#define M_ 256

// ---------------- scratch (no allocs allowed) ----------------
__device__ float g_hproj[B_ * K_];
__device__ float g_a2[B_ * S_];
__device__ __half g_Wh[K_ * C_];

// ---------------- kernel 0: convert W to fp16 ----------------
__global__ void wconv_kernel(const float* __restrict__ Wc) {
    int i = blockIdx.x * 256 + threadIdx.x;   // 512 * 256 = 131072 = K_*C_
    g_Wh[i] = __float2half_rn(Wc[i]);
}

// ---------------- kernel 1: hproj ----------------
__global__ void hproj_kernel(const float* __restrict__ h,
                             const float* __restrict__ Wl,
                             const float* __restrict__ bl) {
    int b = blockIdx.x;
    int k = threadIdx.x;
    __shared__ float hs[M_];
    hs[k] = h[b * M_ + k];
    __syncthreads();
    float s = bl[k];
    const float* wrow = Wl + (size_t)k * M_;
#pragma unroll 8
    for (int m = 0; m < M_; m++) s += hs[m] * wrow[m];
    g_hproj[b * K_ + k] = s;
}

// ---------------- kernel 2: mma.sync fused logits (single-term fp16) ----------
// C[256k x 128s] = W[256x512] @ x[512x128] per (b, stile), fp16 inputs,
// fp32 accumulators, fused tanh + W_attn k-reduction.
// 256 threads = 8 warps: kq = wid>>2 (2 x 64k), ws = wid&3 (4 x 32s).

#define CHUNK_C 64
#define N_CHUNKS (C_ / CHUNK_C)   // 8

// smem stage layout (bytes)
#define PA_ELEM 72                 // W tile pitch in fp16 elems (144B)
#define OFF_A 0
#define PX_WORDS 136               // x-pair tile pitch in u32 words (544B; 136%32==8)
#define OFF_X 36864                // 256*144
#define STAGE_BYTES 54272          // + 32*544
#define DYN_BYTES (2 * STAGE_BYTES)

extern __shared__ __align__(16) char dyn_smem[];

__device__ __forceinline__ uint32_t pack_half2(float lo, float hi) {
    __half2 p = __floats2half2_rn(lo, hi);
    return *(uint32_t*)&p;
}

__device__ __forceinline__ void mma16816(float* d, uint32_t a0, uint32_t a1,
                                         uint32_t a2, uint32_t a3,
                                         uint32_t b0, uint32_t b1) {
    asm volatile(
        "mma.sync.aligned.m16n8k16.row.col.f32.f16.f16.f32 "
        "{%0,%1,%2,%3}, {%4,%5,%6,%7}, {%8,%9}, {%0,%1,%2,%3};"
        : "+f"(d[0]), "+f"(d[1]), "+f"(d[2]), "+f"(d[3])
        : "r"(a0), "r"(a1), "r"(a2), "r"(a3), "r"(b0), "r"(b1));
}

// fill one stage with chunk starting at channel c0
__device__ __forceinline__ void fill_stage(char* st, const float* __restrict__ xb,
                                           int c0, int tid) {
    const int lane = tid & 31;
    const int w    = tid >> 5;
    // --- W tile: [k][c] fp16, pitch 144B, rows k=0..255, 64 c ---
#pragma unroll
    for (int it = 0; it < 8; it++) {
        const int idx = tid + it * 256;           // 0..2047
        const int k   = idx >> 3;
        const int seg = idx & 7;                  // 16B segment
        const uint4 vh = *((const uint4*)(g_Wh + (size_t)k * C_ + c0) + seg);
        *(uint4*)(st + OFF_A + k * 144 + seg * 16) = vh;
    }
    // --- x tile: packed c-pairs. row c2 holds fp16x2{x[2c2][s], x[2c2+1][s]} ---
#pragma unroll
    for (int cc = 0; cc < 4; cc++) {
        const int c2 = w + cc * 8;                // 0..31
        const float* r0 = xb + (size_t)(c0 + 2 * c2) * S_;
        const float* r1 = r0 + S_;
        float4 v0 = *(const float4*)(r0 + lane * 4);
        float4 v1 = *(const float4*)(r1 + lane * 4);
        uint4 ph;
        ph.x = pack_half2(v0.x, v1.x);
        ph.y = pack_half2(v0.y, v1.y);
        ph.z = pack_half2(v0.z, v1.z);
        ph.w = pack_half2(v0.w, v1.w);
        *(uint4*)(st + OFF_X + c2 * 544 + lane * 16) = ph;
    }
}

__global__ __launch_bounds__(256, 1)
void attn_logits_mma(const float* __restrict__ x,
                     const float* __restrict__ Wattn) {
    const int stile = blockIdx.x;     // 0..7
    const int b     = blockIdx.y;     // 0..31
    const int tid   = threadIdx.x;
    const int wid   = tid >> 5;
    const int lane  = tid & 31;
    const int g     = lane >> 2;      // 0..7
    const int t     = lane & 3;       // 0..3
    const int kq    = wid >> 2;       // 0..1 (64-k quadrant)
    const int ws    = wid & 3;        // 0..3 (32-s quadrant)

    __shared__ float a2s[128];
    __shared__ float hp_s[K_];
    __shared__ float wa_s[K_];

    char* tiles = dyn_smem;
    const float* xb = x + (size_t)b * C_ * S_ + (size_t)stile * 128;

    // prologue: fill stage 0 + per-CTA scalars
    fill_stage(tiles, xb, 0, tid);
    hp_s[tid] = g_hproj[b * K_ + tid];
    wa_s[tid] = Wattn[tid];
    if (tid < 128) a2s[tid] = 0.0f;
    __syncthreads();

    float acc[2][4][4][4];
#pragma unroll
    for (int kp = 0; kp < 2; kp++)
#pragma unroll
        for (int i = 0; i < 4; i++)
#pragma unroll
            for (int j = 0; j < 4; j++)
#pragma unroll
                for (int r = 0; r < 4; r++) acc[kp][i][j][r] = 0.0f;

    for (int ch = 0; ch < N_CHUNKS; ch++) {
        const int p = ch & 1;
        if (ch + 1 < N_CHUNKS)
            fill_stage(tiles + (p ^ 1) * STAGE_BYTES, xb, (ch + 1) * CHUNK_C, tid);

        const char* st = tiles + p * STAGE_BYTES;
        const __half* Ah = (const __half*)(st + OFF_A);
        const uint32_t* Xh = (const uint32_t*)(st + OFF_X);

#pragma unroll
        for (int kt = 0; kt < 4; kt++) {          // 16-c step within chunk
            // B fragments (k-major pairs): b0 rows {2t,2t+1}, b1 rows {2t+8,2t+9}
            uint32_t bh[4][2];
#pragma unroll
            for (int j = 0; j < 4; j++) {
                const int s = ws * 32 + j * 8 + g;
                bh[j][0] = Xh[(kt * 8 + t)     * PX_WORDS + s];
                bh[j][1] = Xh[(kt * 8 + t + 4) * PX_WORDS + s];
            }
#pragma unroll
            for (int kp = 0; kp < 2; kp++) {
#pragma unroll
                for (int i = 0; i < 4; i++) {
                    const int k0 = kp * 128 + kq * 64 + i * 16;
                    const __half* arh = Ah + (size_t)(k0 + g) * PA_ELEM + kt * 16 + 2 * t;
                    uint32_t ah0 = *(const uint32_t*)(arh);
                    uint32_t ah1 = *(const uint32_t*)(arh + 8 * PA_ELEM);
                    uint32_t ah2 = *(const uint32_t*)(arh + 8);
                    uint32_t ah3 = *(const uint32_t*)(arh + 8 * PA_ELEM + 8);
#pragma unroll
                    for (int j = 0; j < 4; j++)
                        mma16816(acc[kp][i][j], ah0, ah1, ah2, ah3, bh[j][0], bh[j][1]);
                }
            }
        }
        __syncthreads();
    }

    // ---- epilogue: tanh + W_attn reduction over k ----
    float part[4][2];
#pragma unroll
    for (int j = 0; j < 4; j++) { part[j][0] = 0.0f; part[j][1] = 0.0f; }

#pragma unroll
    for (int kp = 0; kp < 2; kp++)
#pragma unroll
        for (int i = 0; i < 4; i++)
#pragma unroll
            for (int half = 0; half < 2; half++) {
                const int k = kp * 128 + kq * 64 + i * 16 + half * 8 + g;
                const float hp = hp_s[k];
                const float wa = wa_s[k];
#pragma unroll
                for (int j = 0; j < 4; j++) {
#pragma unroll
                    for (int pc = 0; pc < 2; pc++) {
                        const float y = acc[kp][i][j][half * 2 + pc];
                        part[j][pc] += tanhf(y + hp) * wa;
                    }
                }
            }

    // reduce over the 8 g-lanes (same t) via butterfly
#pragma unroll
    for (int m = 4; m <= 16; m <<= 1)
#pragma unroll
        for (int j = 0; j < 4; j++) {
            part[j][0] += __shfl_xor_sync(0xffffffffu, part[j][0], m);
            part[j][1] += __shfl_xor_sync(0xffffffffu, part[j][1], m);
        }

    if (lane < 4) {   // lane == t
#pragma unroll
        for (int j = 0; j < 4; j++) {
            atomicAdd(&a2s[ws * 32 + j * 8 + 2 * lane + 0], part[j][0]);
            atomicAdd(&a2s[ws * 32 + j * 8 + 2 * lane + 1], part[j][1]);
        }
    }
    __syncthreads();
    if (tid < 128) g_a2[b * S_ + stile * 128 + tid] = a2s[tid];
}

// ---------------- kernel 3: softmax ----------------
__global__ void softmax_kernel(float* __restrict__ a3_out) {
    const int b = blockIdx.x;
    const int tid = threadIdx.x;
    __shared__ float red[256];
    float v[4];
#pragma unroll
    for (int i = 0; i < 4; i++) v[i] = g_a2[b * S_ + tid + i * 256];
    float mx = fmaxf(fmaxf(v[0], v[1]), fmaxf(v[2], v[3]));
    red[tid] = mx;
    __syncthreads();
    for (int off = 128; off > 0; off >>= 1) {
        if (tid < off) red[tid] = fmaxf(red[tid], red[tid + off]);
        __syncthreads();
    }
    mx = red[0];
    __syncthreads();
    float s = 0.0f;
#pragma unroll
    for (int i = 0; i < 4; i++) { v[i] = expf(v[i] - mx); s += v[i]; }
    red[tid] = s;
    __syncthreads();
    for (int off = 128; off > 0; off >>= 1) {
        if (tid < off) red[tid] += red[tid + off];
        __syncthreads();
    }
    const float inv = 1.0f / red[0];
#pragma unroll
    for (int i = 0; i < 4; i++)
        a3_out[b * S_ + tid + i * 256] = v[i] * inv;
}

// ---------------- kernel 4: context ----------------
__global__ __launch_bounds__(256)
void context_kernel(const float* __restrict__ x,
                    const float* __restrict__ a3,
                    float* __restrict__ ctx) {
    const int b  = blockIdx.x;
    const int cg = blockIdx.y;                 // 64 groups of 8 channels
    const int w    = threadIdx.x >> 5;
    const int lane = threadIdx.x & 31;
    const int c = cg * 8 + w;
    const float4* xr = (const float4*)(x + ((size_t)b * C_ + c) * S_);
    const float4* ar = (const float4*)(a3 + (size_t)b * S_);
    float s0 = 0, s1 = 0, s2 = 0, s3 = 0;
#pragma unroll
    for (int it = 0; it < 8; it++) {
        float4 xv = xr[lane + it * 32];
        float4 av = ar[lane + it * 32];
        s0 += xv.x * av.x; s1 += xv.y * av.y;
        s2 += xv.z * av.z; s3 += xv.w * av.w;
    }
    float s = (s0 + s1) + (s2 + s3);
#pragma unroll
    for (int off = 16; off > 0; off >>= 1)
        s += __shfl_down_sync(0xffffffffu, s, off);
    if (lane == 0) ctx[b * C_ + c] = s;
}

// ---------------- launch ----------------
extern "C" void kernel_launch(void* const* d_in, const int* in_sizes, int n_in,
                              void* d_out, int out_size) {
    const float* x  = (const float*)d_in[0];
    const float* h  = (const float*)d_in[1];
    const float* Wc = (const float*)d_in[2];
    const float* Wl = (const float*)d_in[3];
    const float* bl = (const float*)d_in[4];
    const float* Wa = (const float*)d_in[5];

    float* out = (float*)d_out;
    float* a3  = out;
    float* ctx = out + B_ * S_;

    cudaFuncSetAttribute(attn_logits_mma,
                         cudaFuncAttributeMaxDynamicSharedMemorySize, DYN_BYTES);

    wconv_kernel<<<512, 256>>>(Wc);
    hproj_kernel<<<B_, 256>>>(h, Wl, bl);
    attn_logits_mma<<<dim3(8, B_), 256, DYN_BYTES>>>(x, Wa);
    softmax_kernel<<<B_, 256>>>(a3);
    context_kernel<<<dim3(B_, 64), 256>>>(x, a3, ctx);
}

// round 6
// speedup vs baseline: 3.0059x; 1.0236x over previous
#include <cuda_runtime.h>
#include <cuda_fp16.h>
#include <math.h>
#include <stdint.h>

#define B_ 32
#define C_ 512
#define S_ 1024
#define K_ 256
#define M_ 256

// ---------------- scratch (no allocs allowed) ----------------
__device__ float g_hproj[B_ * K_];
__device__ float g_a2[B_ * S_];
__device__ __half g_Wh[K_ * C_];

__device__ __forceinline__ uint32_t smem_u32(const void* p) {
    uint32_t a;
    asm("{ .reg .u64 t; cvta.to.shared.u64 t, %1; cvt.u32.u64 %0, t; }" : "=r"(a) : "l"(p));
    return a;
}

// ---------------- kernel 1: fused prep (wconv + zero a2 + hproj) -------------
__global__ void prep_kernel(const float* __restrict__ Wc,
                            const float* __restrict__ h,
                            const float* __restrict__ Wl,
                            const float* __restrict__ bl) {
    const int bid = blockIdx.x;
    const int tid = threadIdx.x;
    if (bid < 512) {
        int i = bid * 256 + tid;          // 131072 = K_*C_
        g_Wh[i] = __float2half_rn(Wc[i]);
        if (bid < 128) g_a2[bid * 256 + tid] = 0.0f;
    } else {
        int b = bid - 512;                // 32 hproj blocks
        int k = tid;
        __shared__ float hs[M_];
        hs[k] = h[b * M_ + k];
        __syncthreads();
        float s = bl[k];
        const float* wrow = Wl + (size_t)k * M_;
#pragma unroll 8
        for (int m = 0; m < M_; m++) s += hs[m] * wrow[m];
        g_hproj[b * K_ + k] = s;
    }
}

// ---------------- kernel 2: mma.sync fused logits, k-split -------------------
// Grid (8 stiles, 32 b, 2 kh). Each CTA: Y[128k x 128s] for its k-half,
// fused tanh + W_attn partial reduction, atomicAdd into g_a2.
// 256 threads = 8 warps: kq = wid>>2 (2 x 64k), ws = wid&3 (4 x 32s).

#define CHUNK_C 64
#define N_CHUNKS (C_ / CHUNK_C)    // 8

#define PA_ELEM 72                  // W tile pitch in fp16 elems (144B)
#define OFF_A 0
#define PX_WORDS 136                // x tile pitch in u32 words (544B)
#define OFF_X 18432                 // 128 rows * 144B
#define STAGE_BYTES 35840           // + 32*544
#define DYN_BYTES (2 * STAGE_BYTES)

extern __shared__ __align__(16) char dyn_smem[];

__device__ __forceinline__ uint32_t pack_half2(float lo, float hi) {
    __half2 p = __floats2half2_rn(lo, hi);
    return *(uint32_t*)&p;
}

__device__ __forceinline__ void mma16816(float* d, uint32_t a0, uint32_t a1,
                                         uint32_t a2, uint32_t a3,
                                         uint32_t b0, uint32_t b1) {
    asm volatile(
        "mma.sync.aligned.m16n8k16.row.col.f32.f16.f16.f32 "
        "{%0,%1,%2,%3}, {%4,%5,%6,%7}, {%8,%9}, {%0,%1,%2,%3};"
        : "+f"(d[0]), "+f"(d[1]), "+f"(d[2]), "+f"(d[3])
        : "r"(a0), "r"(a1), "r"(a2), "r"(a3), "r"(b0), "r"(b1));
}

// async-copy W half-tile (128 k-rows x 64 c) for chunk c0 into stage
__device__ __forceinline__ void fill_W_async(char* st, const __half* __restrict__ Wsrc,
                                             int c0, int tid) {
#pragma unroll
    for (int it = 0; it < 4; it++) {
        const int idx = tid + it * 256;    // 0..1023
        const int k   = idx >> 3;          // 0..127
        const int seg = idx & 7;           // 16B segment
        const uint32_t dst = smem_u32(st + OFF_A + k * 144 + seg * 16);
        const __half* src = Wsrc + (size_t)k * C_ + c0 + seg * 8;
        asm volatile("cp.async.cg.shared.global [%0], [%1], 16;" :: "r"(dst), "l"(src));
    }
    asm volatile("cp.async.commit_group;" ::: "memory");
}

// convert + store x tile (64 c x 128 s as 32 c-pairs) for chunk c0
__device__ __forceinline__ void fill_X(char* st, const float* __restrict__ xb,
                                       int c0, int tid) {
    const int lane = tid & 31;
    const int w    = tid >> 5;
#pragma unroll
    for (int cc = 0; cc < 4; cc++) {
        const int c2 = w + cc * 8;         // 0..31
        const float* r0 = xb + (size_t)(c0 + 2 * c2) * S_;
        const float* r1 = r0 + S_;
        float4 v0 = *(const float4*)(r0 + lane * 4);
        float4 v1 = *(const float4*)(r1 + lane * 4);
        uint4 ph;
        ph.x = pack_half2(v0.x, v1.x);
        ph.y = pack_half2(v0.y, v1.y);
        ph.z = pack_half2(v0.z, v1.z);
        ph.w = pack_half2(v0.w, v1.w);
        *(uint4*)(st + OFF_X + c2 * 544 + lane * 16) = ph;
    }
}

__global__ __launch_bounds__(256, 2)
void attn_logits_mma(const float* __restrict__ x,
                     const float* __restrict__ Wattn) {
    const int stile = blockIdx.x;      // 0..7
    const int b     = blockIdx.y;      // 0..31
    const int kh    = blockIdx.z;      // 0..1 (128-k half)
    const int tid   = threadIdx.x;
    const int wid   = tid >> 5;
    const int lane  = tid & 31;
    const int g     = lane >> 2;       // 0..7
    const int t     = lane & 3;        // 0..3
    const int kq    = wid >> 2;        // 0..1 (64-k quadrant within half)
    const int ws    = wid & 3;         // 0..3 (32-s quadrant)

    __shared__ float a2s[128];
    __shared__ float hp_s[128];
    __shared__ float wa_s[128];

    char* tiles = dyn_smem;
    const float* xb   = x + (size_t)b * C_ * S_ + (size_t)stile * 128;
    const __half* Wsrc = g_Wh + (size_t)kh * 128 * C_;

    // prologue: stage 0 = chunk 0
    fill_W_async(tiles, Wsrc, 0, tid);
    fill_X(tiles, xb, 0, tid);
    if (tid < 128) {
        hp_s[tid] = g_hproj[b * K_ + kh * 128 + tid];
        wa_s[tid] = Wattn[kh * 128 + tid];
        a2s[tid]  = 0.0f;
    }
    asm volatile("cp.async.wait_group 0;" ::: "memory");
    __syncthreads();

    float acc[4][4][4];
#pragma unroll
    for (int i = 0; i < 4; i++)
#pragma unroll
        for (int j = 0; j < 4; j++)
#pragma unroll
            for (int r = 0; r < 4; r++) acc[i][j][r] = 0.0f;

    for (int ch = 0; ch < N_CHUNKS; ch++) {
        const int p = ch & 1;
        if (ch + 1 < N_CHUNKS) {
            fill_W_async(tiles + (p ^ 1) * STAGE_BYTES, Wsrc, (ch + 1) * CHUNK_C, tid);
            fill_X(tiles + (p ^ 1) * STAGE_BYTES, xb, (ch + 1) * CHUNK_C, tid);
        }

        const char* st = tiles + p * STAGE_BYTES;
        const __half* Ah = (const __half*)(st + OFF_A);
        const uint32_t* Xh = (const uint32_t*)(st + OFF_X);

#pragma unroll
        for (int kt = 0; kt < 4; kt++) {
            uint32_t bh[4][2];
#pragma unroll
            for (int j = 0; j < 4; j++) {
                const int s = ws * 32 + j * 8 + g;
                bh[j][0] = Xh[(kt * 8 + t)     * PX_WORDS + s];
                bh[j][1] = Xh[(kt * 8 + t + 4) * PX_WORDS + s];
            }
#pragma unroll
            for (int i = 0; i < 4; i++) {
                const int k0 = kq * 64 + i * 16;
                const __half* arh = Ah + (size_t)(k0 + g) * PA_ELEM + kt * 16 + 2 * t;
                uint32_t ah0 = *(const uint32_t*)(arh);
                uint32_t ah1 = *(const uint32_t*)(arh + 8 * PA_ELEM);
                uint32_t ah2 = *(const uint32_t*)(arh + 8);
                uint32_t ah3 = *(const uint32_t*)(arh + 8 * PA_ELEM + 8);
#pragma unroll
                for (int j = 0; j < 4; j++)
                    mma16816(acc[i][j], ah0, ah1, ah2, ah3, bh[j][0], bh[j][1]);
            }
        }
        if (ch + 1 < N_CHUNKS)
            asm volatile("cp.async.wait_group 0;" ::: "memory");
        __syncthreads();
    }

    // ---- epilogue: tanh + W_attn partial reduction over this k-half ----
    float part[4][2];
#pragma unroll
    for (int j = 0; j < 4; j++) { part[j][0] = 0.0f; part[j][1] = 0.0f; }

#pragma unroll
    for (int i = 0; i < 4; i++)
#pragma unroll
        for (int half = 0; half < 2; half++) {
            const int kl = kq * 64 + i * 16 + half * 8 + g;
            const float hp = hp_s[kl];
            const float wa = wa_s[kl];
#pragma unroll
            for (int j = 0; j < 4; j++) {
#pragma unroll
                for (int pc = 0; pc < 2; pc++) {
                    const float y = acc[i][j][half * 2 + pc];
                    part[j][pc] += tanhf(y + hp) * wa;
                }
            }
        }

    // reduce over the 8 g-lanes (same t)
#pragma unroll
    for (int m = 4; m <= 16; m <<= 1)
#pragma unroll
        for (int j = 0; j < 4; j++) {
            part[j][0] += __shfl_xor_sync(0xffffffffu, part[j][0], m);
            part[j][1] += __shfl_xor_sync(0xffffffffu, part[j][1], m);
        }

    if (lane < 4) {  // lane == t
#pragma unroll
        for (int j = 0; j < 4; j++) {
            atomicAdd(&a2s[ws * 32 + j * 8 + 2 * lane + 0], part[j][0]);
            atomicAdd(&a2s[ws * 32 + j * 8 + 2 * lane + 1], part[j][1]);
        }
    }
    __syncthreads();
    if (tid < 128)
        atomicAdd(&g_a2[b * S_ + stile * 128 + tid], a2s[tid]);
}

// ---------------- kernel 3: softmax ----------------
__global__ void softmax_kernel(float* __restrict__ a3_out) {
    const int b = blockIdx.x;
    const int tid = threadIdx.x;
    __shared__ float red[256];
    float v[4];
#pragma unroll
    for (int i = 0; i < 4; i++) v[i] = g_a2[b * S_ + tid + i * 256];
    float mx = fmaxf(fmaxf(v[0], v[1]), fmaxf(v[2], v[3]));
    red[tid] = mx;
    __syncthreads();
    for (int off = 128; off > 0; off >>= 1) {
        if (tid < off) red[tid] = fmaxf(red[tid], red[tid + off]);
        __syncthreads();
    }
    mx = red[0];
    __syncthreads();
    float s = 0.0f;
#pragma unroll
    for (int i = 0; i < 4; i++) { v[i] = expf(v[i] - mx); s += v[i]; }
    red[tid] = s;
    __syncthreads();
    for (int off = 128; off > 0; off >>= 1) {
        if (tid < off) red[tid] += red[tid + off];
        __syncthreads();
    }
    const float inv = 1.0f / red[0];
#pragma unroll
    for (int i = 0; i < 4; i++)
        a3_out[b * S_ + tid + i * 256] = v[i] * inv;
}

// ---------------- kernel 4: context ----------------
__global__ __launch_bounds__(256)
void context_kernel(const float* __restrict__ x,
                    const float* __restrict__ a3,
                    float* __restrict__ ctx) {
    const int b  = blockIdx.x;
    const int cg = blockIdx.y;                 // 64 groups of 8 channels
    const int w    = threadIdx.x >> 5;
    const int lane = threadIdx.x & 31;
    const int c = cg * 8 + w;
    const float4* xr = (const float4*)(x + ((size_t)b * C_ + c) * S_);
    const float4* ar = (const float4*)(a3 + (size_t)b * S_);
    float s0 = 0, s1 = 0, s2 = 0, s3 = 0;
#pragma unroll
    for (int it = 0; it < 8; it++) {
        float4 xv = xr[lane + it * 32];
        float4 av = ar[lane + it * 32];
        s0 += xv.x * av.x; s1 += xv.y * av.y;
        s2 += xv.z * av.z; s3 += xv.w * av.w;
    }
    float s = (s0 + s1) + (s2 + s3);
#pragma unroll
    for (int off = 16; off > 0; off >>= 1)
        s += __shfl_down_sync(0xffffffffu, s, off);
    if (lane == 0) ctx[b * C_ + c] = s;
}

// ---------------- launch ----------------
extern "C" void kernel_launch(void* const* d_in, const int* in_sizes, int n_in,
                              void* d_out, int out_size) {
    const float* x  = (const float*)d_in[0];
    const float* h  = (const float*)d_in[1];
    const float* Wc = (const float*)d_in[2];
    const float* Wl = (const float*)d_in[3];
    const float* bl = (const float*)d_in[4];
    const float* Wa = (const float*)d_in[5];

    float* out = (float*)d_out;
    float* a3  = out;
    float* ctx = out + B_ * S_;

    cudaFuncSetAttribute(attn_logits_mma,
                         cudaFuncAttributeMaxDynamicSharedMemorySize, DYN_BYTES);

    prep_kernel<<<544, 256>>>(Wc, h, Wl, bl);
    attn_logits_mma<<<dim3(8, B_, 2), 256, DYN_BYTES>>>(x, Wa);
    softmax_kernel<<<B_, 256>>>(a3);
    context_kernel<<<dim3(B_, 64), 256>>>(x, a3, ctx);
}